// round 1
// baseline (speedup 1.0000x reference)
#include <cuda_runtime.h>
#include <math.h>

#define B_    4
#define N_    4096
#define D_    256
#define H_    4
#define HD_   64
#define BH_   16            // B*H
#define ROWS_ 16384         // B*N

// ---------------- scratch (static device allocations; no cudaMalloc) ----------------
__device__ float g_q[BH_ * N_ * HD_];
__device__ float g_k[BH_ * N_ * HD_];
__device__ float g_v[BH_ * N_ * HD_];
__device__ float g_ctx[ROWS_ * D_];
__device__ float g_hcat[ROWS_ * 2 * D_];   // [desc | message]
__device__ float g_h1[ROWS_ * 2 * D_];     // ffn1 out -> LN+GELU in place

// =====================================================================
// Generic SGEMM: C[M,NC] = A[M,K] @ W[NC,K]^T + bias (+ optional resid)
// 64x64 block tile, 256 threads, 4x4 per-thread, BK=16, smem k-major.
// All dims divide tiles evenly (M=16384, NC in {256,512,768}, K in {256,512}).
// =====================================================================
__global__ __launch_bounds__(256) void sgemm_nt(
    const float* __restrict__ A, int lda,
    const float* __restrict__ W, int K,
    const float* __restrict__ bias,
    float* __restrict__ C, int ldc, int colOff,
    const float* __restrict__ resid, int ldr)
{
    __shared__ float As[16][68];
    __shared__ float Bs[16][68];
    const int tid  = threadIdx.x;
    const int tm   = tid >> 4, tn = tid & 15;
    const int row0 = blockIdx.y << 6, col0 = blockIdx.x << 6;
    const int am   = tid >> 2, ak4 = tid & 3;

    const float4* A4 = reinterpret_cast<const float4*>(A + (size_t)(row0 + am) * lda) + ak4;
    const float4* W4 = reinterpret_cast<const float4*>(W + (size_t)(col0 + am) * K) + ak4;

    float acc[4][4] = {};
    for (int k0 = 0; k0 < K; k0 += 16) {
        float4 av = A4[k0 >> 2];
        float4 wv = W4[k0 >> 2];
        As[ak4 * 4 + 0][am] = av.x; As[ak4 * 4 + 1][am] = av.y;
        As[ak4 * 4 + 2][am] = av.z; As[ak4 * 4 + 3][am] = av.w;
        Bs[ak4 * 4 + 0][am] = wv.x; Bs[ak4 * 4 + 1][am] = wv.y;
        Bs[ak4 * 4 + 2][am] = wv.z; Bs[ak4 * 4 + 3][am] = wv.w;
        __syncthreads();
        #pragma unroll
        for (int kk = 0; kk < 16; kk++) {
            float4 a = *reinterpret_cast<const float4*>(&As[kk][tm * 4]);
            float4 b = *reinterpret_cast<const float4*>(&Bs[kk][tn * 4]);
            acc[0][0] += a.x * b.x; acc[0][1] += a.x * b.y; acc[0][2] += a.x * b.z; acc[0][3] += a.x * b.w;
            acc[1][0] += a.y * b.x; acc[1][1] += a.y * b.y; acc[1][2] += a.y * b.z; acc[1][3] += a.y * b.w;
            acc[2][0] += a.z * b.x; acc[2][1] += a.z * b.y; acc[2][2] += a.z * b.z; acc[2][3] += a.z * b.w;
            acc[3][0] += a.w * b.x; acc[3][1] += a.w * b.y; acc[3][2] += a.w * b.z; acc[3][3] += a.w * b.w;
        }
        __syncthreads();
    }

    const int cbase = col0 + tn * 4;
    float4 bz = *reinterpret_cast<const float4*>(bias + cbase);
    #pragma unroll
    for (int i = 0; i < 4; i++) {
        int r = row0 + tm * 4 + i;
        float4 o;
        o.x = acc[i][0] + bz.x; o.y = acc[i][1] + bz.y;
        o.z = acc[i][2] + bz.z; o.w = acc[i][3] + bz.w;
        if (resid) {
            float4 rr = *reinterpret_cast<const float4*>(resid + (size_t)r * ldr + cbase);
            o.x += rr.x; o.y += rr.y; o.z += rr.z; o.w += rr.w;
        }
        *reinterpret_cast<float4*>(C + (size_t)r * ldc + colOff + cbase) = o;
    }
}

// =====================================================================
// QKV GEMM with scatter epilogue into per-head [bh, n, d] layout.
// Weight rows are interleaved as (h, d, {q,k,v}): row = h*192 + d*3 + c.
// =====================================================================
__global__ __launch_bounds__(256) void sgemm_qkv(
    const float* __restrict__ A, const float* __restrict__ W, const float* __restrict__ bias)
{
    __shared__ float As[16][68];
    __shared__ float Bs[16][68];
    const int tid  = threadIdx.x;
    const int tm   = tid >> 4, tn = tid & 15;
    const int row0 = blockIdx.y << 6, col0 = blockIdx.x << 6;
    const int am   = tid >> 2, ak4 = tid & 3;

    const float4* A4 = reinterpret_cast<const float4*>(A + (size_t)(row0 + am) * D_) + ak4;
    const float4* W4 = reinterpret_cast<const float4*>(W + (size_t)(col0 + am) * D_) + ak4;

    float acc[4][4] = {};
    for (int k0 = 0; k0 < D_; k0 += 16) {
        float4 av = A4[k0 >> 2];
        float4 wv = W4[k0 >> 2];
        As[ak4 * 4 + 0][am] = av.x; As[ak4 * 4 + 1][am] = av.y;
        As[ak4 * 4 + 2][am] = av.z; As[ak4 * 4 + 3][am] = av.w;
        Bs[ak4 * 4 + 0][am] = wv.x; Bs[ak4 * 4 + 1][am] = wv.y;
        Bs[ak4 * 4 + 2][am] = wv.z; Bs[ak4 * 4 + 3][am] = wv.w;
        __syncthreads();
        #pragma unroll
        for (int kk = 0; kk < 16; kk++) {
            float4 a = *reinterpret_cast<const float4*>(&As[kk][tm * 4]);
            float4 b = *reinterpret_cast<const float4*>(&Bs[kk][tn * 4]);
            acc[0][0] += a.x * b.x; acc[0][1] += a.x * b.y; acc[0][2] += a.x * b.z; acc[0][3] += a.x * b.w;
            acc[1][0] += a.y * b.x; acc[1][1] += a.y * b.y; acc[1][2] += a.y * b.z; acc[1][3] += a.y * b.w;
            acc[2][0] += a.z * b.x; acc[2][1] += a.z * b.y; acc[2][2] += a.z * b.z; acc[2][3] += a.z * b.w;
            acc[3][0] += a.w * b.x; acc[3][1] += a.w * b.y; acc[3][2] += a.w * b.z; acc[3][3] += a.w * b.w;
        }
        __syncthreads();
    }

    #pragma unroll
    for (int i = 0; i < 4; i++) {
        int r = row0 + tm * 4 + i;
        int b = r >> 12, n = r & (N_ - 1);
        #pragma unroll
        for (int j = 0; j < 4; j++) {
            int c = col0 + tn * 4 + j;
            float v = acc[i][j] + bias[c];
            int h   = c / 192;
            int rem = c - h * 192;
            int d   = rem / 3;
            int cc  = rem - d * 3;
            size_t dst = ((size_t)(b * H_ + h) * N_ + n) * HD_ + d;
            if (cc == 0)       g_q[dst] = v;
            else if (cc == 1)  g_k[dst] = v;
            else               g_v[dst] = v;
        }
    }
}

// =====================================================================
// RoPE (interleaved pairs) on q,k; folds attention scale 1/8 into q.
// keypoints: [2, B, 1, N, 64]  (t=0 cos-like, t=1 sin-like)
// =====================================================================
__global__ __launch_bounds__(256) void rope_scale(const float* __restrict__ kp)
{
    int idx = blockIdx.x * 256 + threadIdx.x;   // over BH*N*32 pairs (exact grid)
    int i  = idx & 31;
    int n  = (idx >> 5) & (N_ - 1);
    int bh = idx >> 17;
    int b  = bh >> 2;
    int d0 = i * 2;

    const float* kpc = kp + ((size_t)b * N_ + n) * HD_ + d0;
    const float* kps = kpc + (size_t)B_ * N_ * HD_;
    float c0 = kpc[0], c1 = kpc[1];
    float s0 = kps[0], s1 = kps[1];

    size_t off = ((size_t)bh * N_ + n) * HD_ + d0;
    float x0 = g_q[off], x1 = g_q[off + 1];
    g_q[off]     = (x0 * c0 - x1 * s0) * 0.125f;
    g_q[off + 1] = (x1 * c1 + x0 * s1) * 0.125f;
    x0 = g_k[off]; x1 = g_k[off + 1];
    g_k[off]     = x0 * c0 - x1 * s0;
    g_k[off + 1] = x1 * c1 + x0 * s1;
}

// copy descriptors into hcat[:, 0:256]
__global__ __launch_bounds__(256) void copy_desc(const float4* __restrict__ d4)
{
    int idx = blockIdx.x * 256 + threadIdx.x;   // ROWS_*64 float4s (exact grid)
    int r = idx >> 6, c = idx & 63;
    reinterpret_cast<float4*>(g_hcat)[(size_t)r * 128 + c] = d4[idx];
}

// =====================================================================
// Flash attention, fp32, online softmax.
// Grid: (N/64, BH). 256 threads = 16x16, 4x4 per-thread tiles.
// smem: Qs/Ks/Pst stride 65 (scalar, conflict-free), Vs stride 68 (float4).
// =====================================================================
#define AT_SMEM_BYTES 67328   // (3*64*65 + 64*68) * 4

__global__ __launch_bounds__(256) void attn_kernel()
{
    extern __shared__ float sm[];
    float* Qs  = sm;              // [64][65]
    float* Ks  = sm + 4160;       // [64][65]
    float* Pst = sm + 8320;       // [64][65]
    float* Vs  = sm + 12480;      // [64][68]

    const int bh = blockIdx.y;
    const int q0 = blockIdx.x << 6;
    const int tid = threadIdx.x;
    const int tm = tid >> 4, tn = tid & 15;

    const float* Qg = g_q + (size_t)bh * N_ * HD_;
    const float* Kg = g_k + (size_t)bh * N_ * HD_;
    const float* Vg = g_v + (size_t)bh * N_ * HD_;

    // load Q tile (scale already folded into g_q)
    for (int it = 0; it < 4; it++) {
        int e = tid + it * 256;
        int m = e >> 4, d4 = e & 15;
        float4 v = reinterpret_cast<const float4*>(Qg + (size_t)(q0 + m) * HD_)[d4];
        float* p = &Qs[m * 65 + d4 * 4];
        p[0] = v.x; p[1] = v.y; p[2] = v.z; p[3] = v.w;
    }

    float acc[4][4] = {};
    float rm[4] = {-1e30f, -1e30f, -1e30f, -1e30f};
    float rs[4] = {};

    const float* Qp0 = Qs + (tm * 4 + 0) * 65;
    const float* Qp1 = Qs + (tm * 4 + 1) * 65;
    const float* Qp2 = Qs + (tm * 4 + 2) * 65;
    const float* Qp3 = Qs + (tm * 4 + 3) * 65;
    const float* Kp0 = Ks + (tn * 4 + 0) * 65;
    const float* Kp1 = Ks + (tn * 4 + 1) * 65;
    const float* Kp2 = Ks + (tn * 4 + 2) * 65;
    const float* Kp3 = Ks + (tn * 4 + 3) * 65;
    const float* Pp0 = Pst + (tm * 4 + 0) * 65;
    const float* Pp1 = Pst + (tm * 4 + 1) * 65;
    const float* Pp2 = Pst + (tm * 4 + 2) * 65;
    const float* Pp3 = Pst + (tm * 4 + 3) * 65;

    for (int kt = 0; kt < N_; kt += 64) {
        __syncthreads();   // prev PV done (Vs/Pst free); Qs ready on first iter
        for (int it = 0; it < 4; it++) {
            int e = tid + it * 256;
            int n = e >> 4, d4 = e & 15;
            float4 kv = reinterpret_cast<const float4*>(Kg + (size_t)(kt + n) * HD_)[d4];
            float* p = &Ks[n * 65 + d4 * 4];
            p[0] = kv.x; p[1] = kv.y; p[2] = kv.z; p[3] = kv.w;
            float4 vv = reinterpret_cast<const float4*>(Vg + (size_t)(kt + n) * HD_)[d4];
            *reinterpret_cast<float4*>(&Vs[n * 68 + d4 * 4]) = vv;
        }
        __syncthreads();

        // S = Q @ K^T (scale pre-folded)
        float S[4][4] = {};
        #pragma unroll 8
        for (int kk = 0; kk < 64; kk++) {
            float a0 = Qp0[kk], a1 = Qp1[kk], a2 = Qp2[kk], a3 = Qp3[kk];
            float b0 = Kp0[kk], b1 = Kp1[kk], b2 = Kp2[kk], b3 = Kp3[kk];
            S[0][0] += a0 * b0; S[0][1] += a0 * b1; S[0][2] += a0 * b2; S[0][3] += a0 * b3;
            S[1][0] += a1 * b0; S[1][1] += a1 * b1; S[1][2] += a1 * b2; S[1][3] += a1 * b3;
            S[2][0] += a2 * b0; S[2][1] += a2 * b1; S[2][2] += a2 * b2; S[2][3] += a2 * b3;
            S[3][0] += a3 * b0; S[3][1] += a3 * b1; S[3][2] += a3 * b2; S[3][3] += a3 * b3;
        }

        // online softmax (16-lane groups share a query row set)
        #pragma unroll
        for (int i = 0; i < 4; i++) {
            float mx = fmaxf(fmaxf(S[i][0], S[i][1]), fmaxf(S[i][2], S[i][3]));
            mx = fmaxf(mx, __shfl_xor_sync(0xffffffffu, mx, 8));
            mx = fmaxf(mx, __shfl_xor_sync(0xffffffffu, mx, 4));
            mx = fmaxf(mx, __shfl_xor_sync(0xffffffffu, mx, 2));
            mx = fmaxf(mx, __shfl_xor_sync(0xffffffffu, mx, 1));
            float nm = fmaxf(rm[i], mx);
            float corr = __expf(rm[i] - nm);
            rm[i] = nm;
            S[i][0] = __expf(S[i][0] - nm);
            S[i][1] = __expf(S[i][1] - nm);
            S[i][2] = __expf(S[i][2] - nm);
            S[i][3] = __expf(S[i][3] - nm);
            float ps = S[i][0] + S[i][1] + S[i][2] + S[i][3];
            ps += __shfl_xor_sync(0xffffffffu, ps, 8);
            ps += __shfl_xor_sync(0xffffffffu, ps, 4);
            ps += __shfl_xor_sync(0xffffffffu, ps, 2);
            ps += __shfl_xor_sync(0xffffffffu, ps, 1);
            rs[i] = rs[i] * corr + ps;
            acc[i][0] *= corr; acc[i][1] *= corr; acc[i][2] *= corr; acc[i][3] *= corr;
            float* pw = &Pst[(tm * 4 + i) * 65 + tn * 4];
            pw[0] = S[i][0]; pw[1] = S[i][1]; pw[2] = S[i][2]; pw[3] = S[i][3];
        }
        __syncthreads();

        // acc += P @ V
        #pragma unroll 8
        for (int n = 0; n < 64; n++) {
            float p0 = Pp0[n], p1 = Pp1[n], p2 = Pp2[n], p3 = Pp3[n];
            float4 v = *reinterpret_cast<const float4*>(&Vs[n * 68 + tn * 4]);
            acc[0][0] += p0 * v.x; acc[0][1] += p0 * v.y; acc[0][2] += p0 * v.z; acc[0][3] += p0 * v.w;
            acc[1][0] += p1 * v.x; acc[1][1] += p1 * v.y; acc[1][2] += p1 * v.z; acc[1][3] += p1 * v.w;
            acc[2][0] += p2 * v.x; acc[2][1] += p2 * v.y; acc[2][2] += p2 * v.z; acc[2][3] += p2 * v.w;
            acc[3][0] += p3 * v.x; acc[3][1] += p3 * v.y; acc[3][2] += p3 * v.z; acc[3][3] += p3 * v.w;
        }
    }

    // epilogue: ctx[b, n, h*64 + d]
    const int b = bh >> 2, h = bh & 3;
    #pragma unroll
    for (int i = 0; i < 4; i++) {
        float inv = 1.0f / rs[i];
        int m = q0 + tm * 4 + i;
        float4 o = make_float4(acc[i][0] * inv, acc[i][1] * inv, acc[i][2] * inv, acc[i][3] * inv);
        *reinterpret_cast<float4*>(&g_ctx[((size_t)(b * N_ + m)) * D_ + h * HD_ + tn * 4]) = o;
    }
}

// =====================================================================
// LayerNorm(512) + exact GELU, in place on g_h1. One block per row.
// =====================================================================
__device__ __forceinline__ float gelu_f(float v)
{
    return 0.5f * v * (1.0f + erff(v * 0.70710678118654752440f));
}

__global__ __launch_bounds__(128) void ln_gelu_kernel(
    const float* __restrict__ gam, const float* __restrict__ bet)
{
    __shared__ float red[4];
    const int r = blockIdx.x;
    float4* row4 = reinterpret_cast<float4*>(g_h1 + (size_t)r * 512);
    const int tid = threadIdx.x;

    float4 x = row4[tid];
    float s = x.x + x.y + x.z + x.w;
    #pragma unroll
    for (int o = 16; o >= 1; o >>= 1) s += __shfl_xor_sync(0xffffffffu, s, o);
    if ((tid & 31) == 0) red[tid >> 5] = s;
    __syncthreads();
    float mu = (red[0] + red[1] + red[2] + red[3]) * (1.0f / 512.0f);
    __syncthreads();

    float dx0 = x.x - mu, dx1 = x.y - mu, dx2 = x.z - mu, dx3 = x.w - mu;
    float sq = dx0 * dx0 + dx1 * dx1 + dx2 * dx2 + dx3 * dx3;
    #pragma unroll
    for (int o = 16; o >= 1; o >>= 1) sq += __shfl_xor_sync(0xffffffffu, sq, o);
    if ((tid & 31) == 0) red[tid >> 5] = sq;
    __syncthreads();
    float var = (red[0] + red[1] + red[2] + red[3]) * (1.0f / 512.0f);
    float rstd = rsqrtf(var + 1e-5f);

    float4 gv = reinterpret_cast<const float4*>(gam)[tid];
    float4 bv = reinterpret_cast<const float4*>(bet)[tid];
    float4 o;
    o.x = gelu_f(dx0 * rstd * gv.x + bv.x);
    o.y = gelu_f(dx1 * rstd * gv.y + bv.y);
    o.z = gelu_f(dx2 * rstd * gv.z + bv.z);
    o.w = gelu_f(dx3 * rstd * gv.w + bv.w);
    row4[tid] = o;
}

// =====================================================================
extern "C" void kernel_launch(void* const* d_in, const int* in_sizes, int n_in,
                              void* d_out, int out_size)
{
    const float* desc   = (const float*)d_in[0];
    const float* kp     = (const float*)d_in[1];
    const float* Wqkv_w = (const float*)d_in[2];
    const float* Wqkv_b = (const float*)d_in[3];
    const float* out_w  = (const float*)d_in[4];
    const float* out_b  = (const float*)d_in[5];
    const float* ffn1_w = (const float*)d_in[6];
    const float* ffn1_b = (const float*)d_in[7];
    const float* ln_g   = (const float*)d_in[8];
    const float* ln_b   = (const float*)d_in[9];
    const float* ffn2_w = (const float*)d_in[10];
    const float* ffn2_b = (const float*)d_in[11];
    float* out = (float*)d_out;

    float *pctx, *phcat, *ph1;
    cudaGetSymbolAddress((void**)&pctx,  g_ctx);
    cudaGetSymbolAddress((void**)&phcat, g_hcat);
    cudaGetSymbolAddress((void**)&ph1,   g_h1);

    cudaFuncSetAttribute((const void*)attn_kernel,
                         cudaFuncAttributeMaxDynamicSharedMemorySize, AT_SMEM_BYTES);

    // 1) fused QKV projection -> per-head q,k,v
    sgemm_qkv<<<dim3(12, 256), 256>>>(desc, Wqkv_w, Wqkv_b);
    // 2) RoPE on q,k (+ fold 1/sqrt(hd) into q)
    rope_scale<<<8192, 256>>>(kp);
    // 3) descriptors -> hcat[:, 0:256]
    copy_desc<<<4096, 256>>>(reinterpret_cast<const float4*>(desc));
    // 4) flash attention -> ctx [B,N,256]
    attn_kernel<<<dim3(64, 16), 256, AT_SMEM_BYTES>>>();
    // 5) out projection -> hcat[:, 256:512]
    sgemm_nt<<<dim3(4, 256), 256>>>(pctx, 256, out_w, 256, out_b, phcat, 512, 256, nullptr, 0);
    // 6) ffn1: hcat @ ffn1_w^T + b -> h1
    sgemm_nt<<<dim3(8, 256), 256>>>(phcat, 512, ffn1_w, 512, ffn1_b, ph1, 512, 0, nullptr, 0);
    // 7) LayerNorm + exact GELU (in place)
    ln_gelu_kernel<<<16384, 128>>>(ln_g, ln_b);
    // 8) ffn2 + residual -> out
    sgemm_nt<<<dim3(4, 256), 256>>>(ph1, 512, ffn2_w, 512, ffn2_b, out, 256, 0, desc, 256);
}

// round 3
// speedup vs baseline: 2.7112x; 2.7112x over previous
#include <cuda_runtime.h>
#include <cuda_fp16.h>
#include <stdint.h>
#include <math.h>

#define B_    4
#define N_    4096
#define D_    256
#define H_    4
#define HD_   64
#define BH_   16            // B*H
#define ROWS_ 16384         // B*N

// ---------------- scratch (static device allocations; no cudaMalloc) ----------------
__device__ float  g_q[BH_ * N_ * HD_];     // fp32 pre-rope q
__device__ float  g_k[BH_ * N_ * HD_];     // fp32 pre-rope k
__device__ __half g_qh[BH_ * N_ * HD_];    // fp16 roped+scaled q
__device__ __half g_kh[BH_ * N_ * HD_];    // fp16 roped k
__device__ __half g_vh[BH_ * N_ * HD_];    // fp16 v
__device__ float  g_ctx[ROWS_ * D_];
__device__ float  g_hcat[ROWS_ * 2 * D_];  // [desc | message]
__device__ float  g_h1[ROWS_ * 2 * D_];    // ffn1 out -> LN+GELU in place

// =====================================================================
// Generic SGEMM: C[M,NC] = A[M,K] @ W[NC,K]^T + bias (+ optional resid)
// =====================================================================
__global__ __launch_bounds__(256) void sgemm_nt(
    const float* __restrict__ A, int lda,
    const float* __restrict__ W, int K,
    const float* __restrict__ bias,
    float* __restrict__ C, int ldc, int colOff,
    const float* __restrict__ resid, int ldr)
{
    __shared__ float As[16][68];
    __shared__ float Bs[16][68];
    const int tid  = threadIdx.x;
    const int tm   = tid >> 4, tn = tid & 15;
    const int row0 = blockIdx.y << 6, col0 = blockIdx.x << 6;
    const int am   = tid >> 2, ak4 = tid & 3;

    const float4* A4 = reinterpret_cast<const float4*>(A + (size_t)(row0 + am) * lda) + ak4;
    const float4* W4 = reinterpret_cast<const float4*>(W + (size_t)(col0 + am) * K) + ak4;

    float acc[4][4] = {};
    for (int k0 = 0; k0 < K; k0 += 16) {
        float4 av = A4[k0 >> 2];
        float4 wv = W4[k0 >> 2];
        As[ak4 * 4 + 0][am] = av.x; As[ak4 * 4 + 1][am] = av.y;
        As[ak4 * 4 + 2][am] = av.z; As[ak4 * 4 + 3][am] = av.w;
        Bs[ak4 * 4 + 0][am] = wv.x; Bs[ak4 * 4 + 1][am] = wv.y;
        Bs[ak4 * 4 + 2][am] = wv.z; Bs[ak4 * 4 + 3][am] = wv.w;
        __syncthreads();
        #pragma unroll
        for (int kk = 0; kk < 16; kk++) {
            float4 a = *reinterpret_cast<const float4*>(&As[kk][tm * 4]);
            float4 b = *reinterpret_cast<const float4*>(&Bs[kk][tn * 4]);
            acc[0][0] += a.x * b.x; acc[0][1] += a.x * b.y; acc[0][2] += a.x * b.z; acc[0][3] += a.x * b.w;
            acc[1][0] += a.y * b.x; acc[1][1] += a.y * b.y; acc[1][2] += a.y * b.z; acc[1][3] += a.y * b.w;
            acc[2][0] += a.z * b.x; acc[2][1] += a.z * b.y; acc[2][2] += a.z * b.z; acc[2][3] += a.z * b.w;
            acc[3][0] += a.w * b.x; acc[3][1] += a.w * b.y; acc[3][2] += a.w * b.z; acc[3][3] += a.w * b.w;
        }
        __syncthreads();
    }

    const int cbase = col0 + tn * 4;
    float4 bz = *reinterpret_cast<const float4*>(bias + cbase);
    #pragma unroll
    for (int i = 0; i < 4; i++) {
        int r = row0 + tm * 4 + i;
        float4 o;
        o.x = acc[i][0] + bz.x; o.y = acc[i][1] + bz.y;
        o.z = acc[i][2] + bz.z; o.w = acc[i][3] + bz.w;
        if (resid) {
            float4 rr = *reinterpret_cast<const float4*>(resid + (size_t)r * ldr + cbase);
            o.x += rr.x; o.y += rr.y; o.z += rr.z; o.w += rr.w;
        }
        *reinterpret_cast<float4*>(C + (size_t)r * ldc + colOff + cbase) = o;
    }
}

// =====================================================================
// QKV GEMM with scatter epilogue into per-head [bh, n, d] layout.
// Weight rows interleaved (h, d, {q,k,v}): row = h*192 + d*3 + c.
// q,k -> fp32 (rope pending); v -> fp16 directly.
// =====================================================================
__global__ __launch_bounds__(256) void sgemm_qkv(
    const float* __restrict__ A, const float* __restrict__ W, const float* __restrict__ bias)
{
    __shared__ float As[16][68];
    __shared__ float Bs[16][68];
    const int tid  = threadIdx.x;
    const int tm   = tid >> 4, tn = tid & 15;
    const int row0 = blockIdx.y << 6, col0 = blockIdx.x << 6;
    const int am   = tid >> 2, ak4 = tid & 3;

    const float4* A4 = reinterpret_cast<const float4*>(A + (size_t)(row0 + am) * D_) + ak4;
    const float4* W4 = reinterpret_cast<const float4*>(W + (size_t)(col0 + am) * D_) + ak4;

    float acc[4][4] = {};
    for (int k0 = 0; k0 < D_; k0 += 16) {
        float4 av = A4[k0 >> 2];
        float4 wv = W4[k0 >> 2];
        As[ak4 * 4 + 0][am] = av.x; As[ak4 * 4 + 1][am] = av.y;
        As[ak4 * 4 + 2][am] = av.z; As[ak4 * 4 + 3][am] = av.w;
        Bs[ak4 * 4 + 0][am] = wv.x; Bs[ak4 * 4 + 1][am] = wv.y;
        Bs[ak4 * 4 + 2][am] = wv.z; Bs[ak4 * 4 + 3][am] = wv.w;
        __syncthreads();
        #pragma unroll
        for (int kk = 0; kk < 16; kk++) {
            float4 a = *reinterpret_cast<const float4*>(&As[kk][tm * 4]);
            float4 b = *reinterpret_cast<const float4*>(&Bs[kk][tn * 4]);
            acc[0][0] += a.x * b.x; acc[0][1] += a.x * b.y; acc[0][2] += a.x * b.z; acc[0][3] += a.x * b.w;
            acc[1][0] += a.y * b.x; acc[1][1] += a.y * b.y; acc[1][2] += a.y * b.z; acc[1][3] += a.y * b.w;
            acc[2][0] += a.z * b.x; acc[2][1] += a.z * b.y; acc[2][2] += a.z * b.z; acc[2][3] += a.z * b.w;
            acc[3][0] += a.w * b.x; acc[3][1] += a.w * b.y; acc[3][2] += a.w * b.z; acc[3][3] += a.w * b.w;
        }
        __syncthreads();
    }

    #pragma unroll
    for (int i = 0; i < 4; i++) {
        int r = row0 + tm * 4 + i;
        int b = r >> 12, n = r & (N_ - 1);
        #pragma unroll
        for (int j = 0; j < 4; j++) {
            int c = col0 + tn * 4 + j;
            float v = acc[i][j] + bias[c];
            int h   = c / 192;
            int rem = c - h * 192;
            int d   = rem / 3;
            int cc  = rem - d * 3;
            size_t dst = ((size_t)(b * H_ + h) * N_ + n) * HD_ + d;
            if (cc == 0)       g_q[dst] = v;
            else if (cc == 1)  g_k[dst] = v;
            else               g_vh[dst] = __float2half(v);
        }
    }
}

// =====================================================================
// RoPE -> fp16 q (with 1/8 scale folded) and fp16 k.
// keypoints: [2, B, 1, N, 64]  (t=0 cos-like, t=1 sin-like)
// =====================================================================
__global__ __launch_bounds__(256) void rope_half(const float* __restrict__ kp)
{
    int idx = blockIdx.x * 256 + threadIdx.x;   // BH*N*32 pairs (exact grid)
    int i  = idx & 31;
    int n  = (idx >> 5) & (N_ - 1);
    int bh = idx >> 17;
    int b  = bh >> 2;
    int d0 = i * 2;

    const float* kpc = kp + ((size_t)b * N_ + n) * HD_ + d0;
    const float* kps = kpc + (size_t)B_ * N_ * HD_;
    float c0 = kpc[0], c1 = kpc[1];
    float s0 = kps[0], s1 = kps[1];

    size_t off = ((size_t)bh * N_ + n) * HD_ + d0;
    float x0 = g_q[off], x1 = g_q[off + 1];
    float q0 = (x0 * c0 - x1 * s0) * 0.125f;
    float q1 = (x1 * c1 + x0 * s1) * 0.125f;
    *reinterpret_cast<__half2*>(&g_qh[off]) = __floats2half2_rn(q0, q1);

    x0 = g_k[off]; x1 = g_k[off + 1];
    float k0 = x0 * c0 - x1 * s0;
    float k1 = x1 * c1 + x0 * s1;
    *reinterpret_cast<__half2*>(&g_kh[off]) = __floats2half2_rn(k0, k1);
}

// copy descriptors into hcat[:, 0:256]
__global__ __launch_bounds__(256) void copy_desc(const float4* __restrict__ d4)
{
    int idx = blockIdx.x * 256 + threadIdx.x;   // ROWS_*64 float4s (exact grid)
    int r = idx >> 6, c = idx & 63;
    reinterpret_cast<float4*>(g_hcat)[(size_t)r * 128 + c] = d4[idx];
}

// =====================================================================
// Tensor-core flash attention (fp16 mma.sync.m16n8k16, fp32 softmax).
// Grid: (N/128, BH), 256 threads = 8 warps, each warp owns 16 query rows.
// Key tile BN=64. smem stride 72 halves -> conflict-free ldmatrix.
// =====================================================================
#define ATT_BM 128
#define ATT_BN 64

__device__ __forceinline__ void ldsm_x4(uint32_t& r0, uint32_t& r1, uint32_t& r2, uint32_t& r3,
                                        const __half* p)
{
    uint32_t addr = (uint32_t)__cvta_generic_to_shared(p);
    asm volatile("ldmatrix.sync.aligned.m8n8.x4.shared.b16 {%0,%1,%2,%3}, [%4];"
                 : "=r"(r0), "=r"(r1), "=r"(r2), "=r"(r3) : "r"(addr));
}

__device__ __forceinline__ void ldsm_x4_t(uint32_t& r0, uint32_t& r1, uint32_t& r2, uint32_t& r3,
                                          const __half* p)
{
    uint32_t addr = (uint32_t)__cvta_generic_to_shared(p);
    asm volatile("ldmatrix.sync.aligned.m8n8.x4.trans.shared.b16 {%0,%1,%2,%3}, [%4];"
                 : "=r"(r0), "=r"(r1), "=r"(r2), "=r"(r3) : "r"(addr));
}

__device__ __forceinline__ void mma16816(float* d, const uint32_t* a, uint32_t b0, uint32_t b1)
{
    asm volatile("mma.sync.aligned.m16n8k16.row.col.f32.f16.f16.f32 "
                 "{%0,%1,%2,%3}, {%4,%5,%6,%7}, {%8,%9}, {%0,%1,%2,%3};"
                 : "+f"(d[0]), "+f"(d[1]), "+f"(d[2]), "+f"(d[3])
                 : "r"(a[0]), "r"(a[1]), "r"(a[2]), "r"(a[3]), "r"(b0), "r"(b1));
}

__global__ __launch_bounds__(256) void attn_mma()
{
    __shared__ __half sK[64][72];
    __shared__ __half sV[64][72];

    const int tid  = threadIdx.x;
    const int warp = tid >> 5, lane = tid & 31;
    const int bh   = blockIdx.y;
    const int q0   = blockIdx.x * ATT_BM;

    const __half* Qg = g_qh + (size_t)bh * N_ * HD_;
    const __half* Kg = g_kh + (size_t)bh * N_ * HD_;
    const __half* Vg = g_vh + (size_t)bh * N_ * HD_;

    // ---- stage Q (rows 0-63 in sK, 64-127 in sV), hoist A-fragments ----
    #pragma unroll
    for (int it = 0; it < 4; it++) {
        int idx = tid + it * 256;              // 0..1023
        int row = idx >> 3, c8 = idx & 7;
        float4 v = *reinterpret_cast<const float4*>(Qg + (size_t)(q0 + row) * HD_ + c8 * 8);
        __half* dst = (row < 64) ? &sK[row][c8 * 8] : &sV[row - 64][c8 * 8];
        *reinterpret_cast<float4*>(dst) = v;
    }
    __syncthreads();

    uint32_t qf[4][4];
    {
        const __half (*Qa)[72] = (warp < 4) ? sK : sV;
        int lr = (warp & 3) * 16 + (lane & 15);
        int ch = (lane >> 4) * 8;
        #pragma unroll
        for (int kk = 0; kk < 4; kk++)
            ldsm_x4(qf[kk][0], qf[kk][1], qf[kk][2], qf[kk][3], &Qa[lr][kk * 16 + ch]);
    }
    __syncthreads();

    float vacc[8][4] = {};
    float rm[2] = {-1e30f, -1e30f};
    float rl[2] = {0.0f, 0.0f};

    for (int kt = 0; kt < N_; kt += ATT_BN) {
        // ---- load K,V tile ----
        #pragma unroll
        for (int it = 0; it < 2; it++) {
            int idx = tid + it * 256;          // 0..511
            int row = idx >> 3, c8 = idx & 7;
            *reinterpret_cast<float4*>(&sK[row][c8 * 8]) =
                *reinterpret_cast<const float4*>(Kg + (size_t)(kt + row) * HD_ + c8 * 8);
            *reinterpret_cast<float4*>(&sV[row][c8 * 8]) =
                *reinterpret_cast<const float4*>(Vg + (size_t)(kt + row) * HD_ + c8 * 8);
        }
        __syncthreads();

        // ---- S = Q @ K^T ----
        float sacc[8][4] = {};
        #pragma unroll
        for (int kk = 0; kk < 4; kk++) {
            #pragma unroll
            for (int nt = 0; nt < 8; nt += 2) {
                int n = nt * 8 + (lane & 7) + ((lane >> 4) << 3);
                int k = kk * 16 + (((lane >> 3) & 1) << 3);
                uint32_t b0, b1, b2, b3;
                ldsm_x4(b0, b1, b2, b3, &sK[n][k]);
                mma16816(sacc[nt],     qf[kk], b0, b1);
                mma16816(sacc[nt + 1], qf[kk], b2, b3);
            }
        }

        // ---- online softmax (each lane: rows lane/4 and lane/4+8; 4 lanes/row) ----
        uint32_t pf[8][2];
        #pragma unroll
        for (int i = 0; i < 2; i++) {
            float mx = -1e30f;
            #pragma unroll
            for (int nt = 0; nt < 8; nt++)
                mx = fmaxf(mx, fmaxf(sacc[nt][2 * i], sacc[nt][2 * i + 1]));
            mx = fmaxf(mx, __shfl_xor_sync(0xffffffffu, mx, 1));
            mx = fmaxf(mx, __shfl_xor_sync(0xffffffffu, mx, 2));
            float nm   = fmaxf(rm[i], mx);
            float corr = __expf(rm[i] - nm);
            rm[i] = nm;
            float ps = 0.0f;
            #pragma unroll
            for (int nt = 0; nt < 8; nt++) {
                float e0 = __expf(sacc[nt][2 * i]     - nm);
                float e1 = __expf(sacc[nt][2 * i + 1] - nm);
                ps += e0 + e1;
                __half2 h = __floats2half2_rn(e0, e1);
                pf[nt][i] = *reinterpret_cast<uint32_t*>(&h);
            }
            ps += __shfl_xor_sync(0xffffffffu, ps, 1);
            ps += __shfl_xor_sync(0xffffffffu, ps, 2);
            rl[i] = rl[i] * corr + ps;
            #pragma unroll
            for (int nt = 0; nt < 8; nt++) {
                vacc[nt][2 * i]     *= corr;
                vacc[nt][2 * i + 1] *= corr;
            }
        }

        // ---- ctx += P @ V ----
        #pragma unroll
        for (int kk2 = 0; kk2 < 4; kk2++) {
            uint32_t af[4] = {pf[2 * kk2][0], pf[2 * kk2][1], pf[2 * kk2 + 1][0], pf[2 * kk2 + 1][1]};
            #pragma unroll
            for (int nt = 0; nt < 8; nt += 2) {
                int k = kk2 * 16 + (lane & 15);
                int n = nt * 8 + ((lane >> 4) << 3);
                uint32_t b0, b1, b2, b3;
                ldsm_x4_t(b0, b1, b2, b3, &sV[k][n]);
                mma16816(vacc[nt],     af, b0, b1);
                mma16816(vacc[nt + 1], af, b2, b3);
            }
        }
        __syncthreads();
    }

    // ---- epilogue: ctx[b, n, h*64 + d] ----
    const int b = bh >> 2, h = bh & 3;
    #pragma unroll
    for (int i = 0; i < 2; i++) {
        float inv = 1.0f / rl[i];
        int m = q0 + warp * 16 + (lane >> 2) + i * 8;
        float* dst = &g_ctx[((size_t)(b * N_ + m)) * D_ + h * HD_];
        #pragma unroll
        for (int nt = 0; nt < 8; nt++) {
            int c = nt * 8 + (lane & 3) * 2;
            *reinterpret_cast<float2*>(&dst[c]) =
                make_float2(vacc[nt][2 * i] * inv, vacc[nt][2 * i + 1] * inv);
        }
    }
}

// =====================================================================
// LayerNorm(512) + exact GELU, in place on g_h1. One block per row.
// =====================================================================
__device__ __forceinline__ float gelu_f(float v)
{
    return 0.5f * v * (1.0f + erff(v * 0.70710678118654752440f));
}

__global__ __launch_bounds__(128) void ln_gelu_kernel(
    const float* __restrict__ gam, const float* __restrict__ bet)
{
    __shared__ float red[4];
    const int r = blockIdx.x;
    float4* row4 = reinterpret_cast<float4*>(g_h1 + (size_t)r * 512);
    const int tid = threadIdx.x;

    float4 x = row4[tid];
    float s = x.x + x.y + x.z + x.w;
    #pragma unroll
    for (int o = 16; o >= 1; o >>= 1) s += __shfl_xor_sync(0xffffffffu, s, o);
    if ((tid & 31) == 0) red[tid >> 5] = s;
    __syncthreads();
    float mu = (red[0] + red[1] + red[2] + red[3]) * (1.0f / 512.0f);
    __syncthreads();

    float dx0 = x.x - mu, dx1 = x.y - mu, dx2 = x.z - mu, dx3 = x.w - mu;
    float sq = dx0 * dx0 + dx1 * dx1 + dx2 * dx2 + dx3 * dx3;
    #pragma unroll
    for (int o = 16; o >= 1; o >>= 1) sq += __shfl_xor_sync(0xffffffffu, sq, o);
    if ((tid & 31) == 0) red[tid >> 5] = sq;
    __syncthreads();
    float var = (red[0] + red[1] + red[2] + red[3]) * (1.0f / 512.0f);
    float rstd = rsqrtf(var + 1e-5f);

    float4 gv = reinterpret_cast<const float4*>(gam)[tid];
    float4 bv = reinterpret_cast<const float4*>(bet)[tid];
    float4 o;
    o.x = gelu_f(dx0 * rstd * gv.x + bv.x);
    o.y = gelu_f(dx1 * rstd * gv.y + bv.y);
    o.z = gelu_f(dx2 * rstd * gv.z + bv.z);
    o.w = gelu_f(dx3 * rstd * gv.w + bv.w);
    row4[tid] = o;
}

// =====================================================================
extern "C" void kernel_launch(void* const* d_in, const int* in_sizes, int n_in,
                              void* d_out, int out_size)
{
    const float* desc   = (const float*)d_in[0];
    const float* kp     = (const float*)d_in[1];
    const float* Wqkv_w = (const float*)d_in[2];
    const float* Wqkv_b = (const float*)d_in[3];
    const float* out_w  = (const float*)d_in[4];
    const float* out_b  = (const float*)d_in[5];
    const float* ffn1_w = (const float*)d_in[6];
    const float* ffn1_b = (const float*)d_in[7];
    const float* ln_g   = (const float*)d_in[8];
    const float* ln_b   = (const float*)d_in[9];
    const float* ffn2_w = (const float*)d_in[10];
    const float* ffn2_b = (const float*)d_in[11];
    float* out = (float*)d_out;

    float *pctx, *phcat, *ph1;
    cudaGetSymbolAddress((void**)&pctx,  g_ctx);
    cudaGetSymbolAddress((void**)&phcat, g_hcat);
    cudaGetSymbolAddress((void**)&ph1,   g_h1);

    // 1) fused QKV projection -> fp32 q,k + fp16 v (per-head layout)
    sgemm_qkv<<<dim3(12, 256), 256>>>(desc, Wqkv_w, Wqkv_b);
    // 2) RoPE -> fp16 q (scaled), fp16 k
    rope_half<<<8192, 256>>>(kp);
    // 3) descriptors -> hcat[:, 0:256]
    copy_desc<<<4096, 256>>>(reinterpret_cast<const float4*>(desc));
    // 4) tensor-core flash attention -> ctx [B,N,256]
    attn_mma<<<dim3(N_ / ATT_BM, BH_), 256>>>();
    // 5) out projection -> hcat[:, 256:512]
    sgemm_nt<<<dim3(4, 256), 256>>>(pctx, 256, out_w, 256, out_b, phcat, 512, 256, nullptr, 0);
    // 6) ffn1: hcat @ ffn1_w^T + b -> h1
    sgemm_nt<<<dim3(8, 256), 256>>>(phcat, 512, ffn1_w, 512, ffn1_b, ph1, 512, 0, nullptr, 0);
    // 7) LayerNorm + exact GELU (in place)
    ln_gelu_kernel<<<16384, 128>>>(ln_g, ln_b);
    // 8) ffn2 + residual -> out
    sgemm_nt<<<dim3(4, 256), 256>>>(ph1, 512, ffn2_w, 512, ffn2_b, out, 256, 0, desc, 256);
}

// round 4
// speedup vs baseline: 5.0689x; 1.8696x over previous
#include <cuda_runtime.h>
#include <cuda_fp16.h>
#include <stdint.h>
#include <math.h>

#define B_    4
#define N_    4096
#define D_    256
#define H_    4
#define HD_   64
#define BH_   16            // B*H
#define ROWS_ 16384         // B*N

// ---------------- scratch (static device allocations; no cudaMalloc) ----------------
__device__ __half g_qh[BH_ * N_ * HD_];      // fp16 q (pre-rope -> roped+scaled in place)
__device__ __half g_kh[BH_ * N_ * HD_];      // fp16 k (pre-rope -> roped in place)
__device__ __half g_vh[BH_ * N_ * HD_];      // fp16 v
__device__ __half g_ctxh[ROWS_ * D_];        // fp16 attention context
__device__ __half g_hcath[ROWS_ * 2 * D_];   // fp16 [desc | message]
__device__ float  g_h1[ROWS_ * 2 * D_];      // ffn1 out fp32 (LN input)
__device__ __half g_h1h[ROWS_ * 2 * D_];     // LN+GELU out fp16 (ffn2 input)
// fp16 weights
__device__ __half g_wqkv_h[3 * D_ * D_];     // 768x256
__device__ __half g_outw_h[D_ * D_];         // 256x256
__device__ __half g_ffn1_h[2 * D_ * 2 * D_]; // 512x512
__device__ __half g_ffn2_h[D_ * 2 * D_];     // 256x512

// ---------------- mma / ldmatrix primitives ----------------
__device__ __forceinline__ void ldsm_x4(uint32_t& r0, uint32_t& r1, uint32_t& r2, uint32_t& r3,
                                        const __half* p)
{
    uint32_t addr = (uint32_t)__cvta_generic_to_shared(p);
    asm volatile("ldmatrix.sync.aligned.m8n8.x4.shared.b16 {%0,%1,%2,%3}, [%4];"
                 : "=r"(r0), "=r"(r1), "=r"(r2), "=r"(r3) : "r"(addr));
}

__device__ __forceinline__ void ldsm_x4_t(uint32_t& r0, uint32_t& r1, uint32_t& r2, uint32_t& r3,
                                          const __half* p)
{
    uint32_t addr = (uint32_t)__cvta_generic_to_shared(p);
    asm volatile("ldmatrix.sync.aligned.m8n8.x4.trans.shared.b16 {%0,%1,%2,%3}, [%4];"
                 : "=r"(r0), "=r"(r1), "=r"(r2), "=r"(r3) : "r"(addr));
}

__device__ __forceinline__ void mma16816(float* d, const uint32_t* a, uint32_t b0, uint32_t b1)
{
    asm volatile("mma.sync.aligned.m16n8k16.row.col.f32.f16.f16.f32 "
                 "{%0,%1,%2,%3}, {%4,%5,%6,%7}, {%8,%9}, {%0,%1,%2,%3};"
                 : "+f"(d[0]), "+f"(d[1]), "+f"(d[2]), "+f"(d[3])
                 : "r"(a[0]), "r"(a[1]), "r"(a[2]), "r"(a[3]), "r"(b0), "r"(b1));
}

// =====================================================================
// fp32 -> fp16 conversion (weights)
// =====================================================================
__global__ __launch_bounds__(256) void f2h(const float4* __restrict__ src,
                                           __half* __restrict__ dst, int n4)
{
    int i = blockIdx.x * 256 + threadIdx.x;
    if (i < n4) {
        float4 v = src[i];
        *reinterpret_cast<__half2*>(&dst[i * 4])     = __floats2half2_rn(v.x, v.y);
        *reinterpret_cast<__half2*>(&dst[i * 4 + 2]) = __floats2half2_rn(v.z, v.w);
    }
}

// descriptors -> fp16 hcat[:, 0:256]
__global__ __launch_bounds__(256) void copy_desc_h(const float4* __restrict__ d4)
{
    int idx = blockIdx.x * 256 + threadIdx.x;   // ROWS_*64 float4 chunks (exact grid)
    int r = idx >> 6, c = idx & 63;
    float4 v = d4[idx];
    __half* dst = &g_hcath[(size_t)r * 512 + c * 4];
    *reinterpret_cast<__half2*>(dst)     = __floats2half2_rn(v.x, v.y);
    *reinterpret_cast<__half2*>(dst + 2) = __floats2half2_rn(v.z, v.w);
}

// =====================================================================
// fp16 tensor-core GEMM: C[M,NC] = A[M,K] @ W[NC,K]^T + bias
// BM=128, BN=128, BK=64, 256 threads = 8 warps (2m x 4n), warp tile 64x32.
// mode 0: float out (+optional resid)   mode 1: half out   mode 2: qkv scatter
// =====================================================================
__global__ __launch_bounds__(256) void hgemm_nt(
    const __half* __restrict__ A, int lda,
    const __half* __restrict__ W, int K,
    const float* __restrict__ bias,
    void* __restrict__ Cv, int ldc, int colOff,
    const float* __restrict__ resid, int mode)
{
    __shared__ __half sA[128][72];
    __shared__ __half sB[128][72];

    const int tid  = threadIdx.x;
    const int warp = tid >> 5, lane = tid & 31;
    const int row0 = blockIdx.y << 7, col0 = blockIdx.x << 7;
    const int m0w  = (warp >> 2) * 64, n0w = (warp & 3) * 32;

    float acc[4][4][4] = {};

    for (int k0 = 0; k0 < K; k0 += 64) {
        // load A/B tiles: 128x64 halves each = 1024 uint4; 256 threads x4
        #pragma unroll
        for (int it = 0; it < 4; it++) {
            int idx = tid + it * 256;
            int row = idx >> 3, c8 = idx & 7;
            *reinterpret_cast<uint4*>(&sA[row][c8 * 8]) =
                *reinterpret_cast<const uint4*>(A + (size_t)(row0 + row) * lda + k0 + c8 * 8);
            *reinterpret_cast<uint4*>(&sB[row][c8 * 8]) =
                *reinterpret_cast<const uint4*>(W + (size_t)(col0 + row) * K + k0 + c8 * 8);
        }
        __syncthreads();

        #pragma unroll
        for (int kk = 0; kk < 4; kk++) {
            uint32_t af[4][4];
            #pragma unroll
            for (int mt = 0; mt < 4; mt++)
                ldsm_x4(af[mt][0], af[mt][1], af[mt][2], af[mt][3],
                        &sA[m0w + mt * 16 + (lane & 15)][kk * 16 + ((lane >> 4) << 3)]);
            #pragma unroll
            for (int np = 0; np < 2; np++) {
                uint32_t b0, b1, b2, b3;
                ldsm_x4(b0, b1, b2, b3,
                        &sB[n0w + np * 16 + (lane & 7) + ((lane >> 4) << 3)]
                           [kk * 16 + (((lane >> 3) & 1) << 3)]);
                #pragma unroll
                for (int mt = 0; mt < 4; mt++) {
                    mma16816(acc[mt][np * 2],     af[mt], b0, b1);
                    mma16816(acc[mt][np * 2 + 1], af[mt], b2, b3);
                }
            }
        }
        __syncthreads();
    }

    // ---------------- epilogue ----------------
    if (mode == 2) {
        // qkv scatter: col c decodes to (h, d, {q,k,v}); rows decode to (b, n)
        #pragma unroll
        for (int mt = 0; mt < 4; mt++) {
            #pragma unroll
            for (int nt = 0; nt < 4; nt++) {
                #pragma unroll
                for (int e = 0; e < 4; e++) {
                    int r = row0 + m0w + mt * 16 + (lane >> 2) + ((e >> 1) << 3);
                    int c = col0 + n0w + nt * 8 + (lane & 3) * 2 + (e & 1);
                    float v = acc[mt][nt][e] + bias[c];
                    int b = r >> 12, n = r & (N_ - 1);
                    int h   = c / 192;
                    int rem = c - h * 192;
                    int d   = rem / 3;
                    int cc  = rem - d * 3;
                    size_t dst = ((size_t)(b * H_ + h) * N_ + n) * HD_ + d;
                    __half hv = __float2half(v);
                    if (cc == 0)       g_qh[dst] = hv;
                    else if (cc == 1)  g_kh[dst] = hv;
                    else               g_vh[dst] = hv;
                }
            }
        }
    } else if (mode == 1) {
        __half* C = (__half*)Cv;
        #pragma unroll
        for (int mt = 0; mt < 4; mt++) {
            #pragma unroll
            for (int i = 0; i < 2; i++) {
                int r = row0 + m0w + mt * 16 + (lane >> 2) + i * 8;
                #pragma unroll
                for (int nt = 0; nt < 4; nt++) {
                    int c = col0 + n0w + nt * 8 + (lane & 3) * 2;
                    float v0 = acc[mt][nt][2 * i]     + bias[c];
                    float v1 = acc[mt][nt][2 * i + 1] + bias[c + 1];
                    *reinterpret_cast<__half2*>(&C[(size_t)r * ldc + colOff + c]) =
                        __floats2half2_rn(v0, v1);
                }
            }
        }
    } else {
        float* C = (float*)Cv;
        #pragma unroll
        for (int mt = 0; mt < 4; mt++) {
            #pragma unroll
            for (int i = 0; i < 2; i++) {
                int r = row0 + m0w + mt * 16 + (lane >> 2) + i * 8;
                #pragma unroll
                for (int nt = 0; nt < 4; nt++) {
                    int c = col0 + n0w + nt * 8 + (lane & 3) * 2;
                    float v0 = acc[mt][nt][2 * i]     + bias[c];
                    float v1 = acc[mt][nt][2 * i + 1] + bias[c + 1];
                    if (resid) {
                        const float2 rr = *reinterpret_cast<const float2*>(
                            &resid[(size_t)r * D_ + c]);
                        v0 += rr.x; v1 += rr.y;
                    }
                    *reinterpret_cast<float2*>(&C[(size_t)r * ldc + colOff + c]) =
                        make_float2(v0, v1);
                }
            }
        }
    }
}

// =====================================================================
// RoPE in place on fp16 q (+1/8 scale) and fp16 k.
// keypoints: [2, B, 1, N, 64]  (t=0 cos-like, t=1 sin-like)
// =====================================================================
__global__ __launch_bounds__(256) void rope_half(const float* __restrict__ kp)
{
    int idx = blockIdx.x * 256 + threadIdx.x;   // BH*N*32 pairs (exact grid)
    int i  = idx & 31;
    int n  = (idx >> 5) & (N_ - 1);
    int bh = idx >> 17;
    int b  = bh >> 2;
    int d0 = i * 2;

    const float* kpc = kp + ((size_t)b * N_ + n) * HD_ + d0;
    const float* kps = kpc + (size_t)B_ * N_ * HD_;
    float c0 = kpc[0], c1 = kpc[1];
    float s0 = kps[0], s1 = kps[1];

    size_t off = ((size_t)bh * N_ + n) * HD_ + d0;
    __half2 qv = *reinterpret_cast<__half2*>(&g_qh[off]);
    float x0 = __low2float(qv), x1 = __high2float(qv);
    *reinterpret_cast<__half2*>(&g_qh[off]) =
        __floats2half2_rn((x0 * c0 - x1 * s0) * 0.125f, (x1 * c1 + x0 * s1) * 0.125f);

    __half2 kv = *reinterpret_cast<__half2*>(&g_kh[off]);
    x0 = __low2float(kv); x1 = __high2float(kv);
    *reinterpret_cast<__half2*>(&g_kh[off]) =
        __floats2half2_rn(x0 * c0 - x1 * s0, x1 * c1 + x0 * s1);
}

// =====================================================================
// Tensor-core flash attention (fp16 mma, fp32 softmax). ctx -> fp16.
// =====================================================================
#define ATT_BM 128
#define ATT_BN 64

__global__ __launch_bounds__(256) void attn_mma()
{
    __shared__ __half sK[64][72];
    __shared__ __half sV[64][72];

    const int tid  = threadIdx.x;
    const int warp = tid >> 5, lane = tid & 31;
    const int bh   = blockIdx.y;
    const int q0   = blockIdx.x * ATT_BM;

    const __half* Qg = g_qh + (size_t)bh * N_ * HD_;
    const __half* Kg = g_kh + (size_t)bh * N_ * HD_;
    const __half* Vg = g_vh + (size_t)bh * N_ * HD_;

    // ---- stage Q (rows 0-63 in sK, 64-127 in sV), hoist A-fragments ----
    #pragma unroll
    for (int it = 0; it < 4; it++) {
        int idx = tid + it * 256;              // 0..1023
        int row = idx >> 3, c8 = idx & 7;
        uint4 v = *reinterpret_cast<const uint4*>(Qg + (size_t)(q0 + row) * HD_ + c8 * 8);
        __half* dst = (row < 64) ? &sK[row][c8 * 8] : &sV[row - 64][c8 * 8];
        *reinterpret_cast<uint4*>(dst) = v;
    }
    __syncthreads();

    uint32_t qf[4][4];
    {
        const __half (*Qa)[72] = (warp < 4) ? sK : sV;
        int lr = (warp & 3) * 16 + (lane & 15);
        int ch = (lane >> 4) * 8;
        #pragma unroll
        for (int kk = 0; kk < 4; kk++)
            ldsm_x4(qf[kk][0], qf[kk][1], qf[kk][2], qf[kk][3], &Qa[lr][kk * 16 + ch]);
    }
    __syncthreads();

    float vacc[8][4] = {};
    float rm[2] = {-1e30f, -1e30f};
    float rl[2] = {0.0f, 0.0f};

    for (int kt = 0; kt < N_; kt += ATT_BN) {
        #pragma unroll
        for (int it = 0; it < 2; it++) {
            int idx = tid + it * 256;          // 0..511
            int row = idx >> 3, c8 = idx & 7;
            *reinterpret_cast<uint4*>(&sK[row][c8 * 8]) =
                *reinterpret_cast<const uint4*>(Kg + (size_t)(kt + row) * HD_ + c8 * 8);
            *reinterpret_cast<uint4*>(&sV[row][c8 * 8]) =
                *reinterpret_cast<const uint4*>(Vg + (size_t)(kt + row) * HD_ + c8 * 8);
        }
        __syncthreads();

        // ---- S = Q @ K^T ----
        float sacc[8][4] = {};
        #pragma unroll
        for (int kk = 0; kk < 4; kk++) {
            #pragma unroll
            for (int nt = 0; nt < 8; nt += 2) {
                int n = nt * 8 + (lane & 7) + ((lane >> 4) << 3);
                int k = kk * 16 + (((lane >> 3) & 1) << 3);
                uint32_t b0, b1, b2, b3;
                ldsm_x4(b0, b1, b2, b3, &sK[n][k]);
                mma16816(sacc[nt],     qf[kk], b0, b1);
                mma16816(sacc[nt + 1], qf[kk], b2, b3);
            }
        }

        // ---- online softmax ----
        uint32_t pf[8][2];
        #pragma unroll
        for (int i = 0; i < 2; i++) {
            float mx = -1e30f;
            #pragma unroll
            for (int nt = 0; nt < 8; nt++)
                mx = fmaxf(mx, fmaxf(sacc[nt][2 * i], sacc[nt][2 * i + 1]));
            mx = fmaxf(mx, __shfl_xor_sync(0xffffffffu, mx, 1));
            mx = fmaxf(mx, __shfl_xor_sync(0xffffffffu, mx, 2));
            float nm   = fmaxf(rm[i], mx);
            float corr = __expf(rm[i] - nm);
            rm[i] = nm;
            float ps = 0.0f;
            #pragma unroll
            for (int nt = 0; nt < 8; nt++) {
                float e0 = __expf(sacc[nt][2 * i]     - nm);
                float e1 = __expf(sacc[nt][2 * i + 1] - nm);
                ps += e0 + e1;
                __half2 h = __floats2half2_rn(e0, e1);
                pf[nt][i] = *reinterpret_cast<uint32_t*>(&h);
            }
            ps += __shfl_xor_sync(0xffffffffu, ps, 1);
            ps += __shfl_xor_sync(0xffffffffu, ps, 2);
            rl[i] = rl[i] * corr + ps;
            #pragma unroll
            for (int nt = 0; nt < 8; nt++) {
                vacc[nt][2 * i]     *= corr;
                vacc[nt][2 * i + 1] *= corr;
            }
        }

        // ---- ctx += P @ V ----
        #pragma unroll
        for (int kk2 = 0; kk2 < 4; kk2++) {
            uint32_t af[4] = {pf[2 * kk2][0], pf[2 * kk2][1], pf[2 * kk2 + 1][0], pf[2 * kk2 + 1][1]};
            #pragma unroll
            for (int nt = 0; nt < 8; nt += 2) {
                int k = kk2 * 16 + (lane & 15);
                int n = nt * 8 + ((lane >> 4) << 3);
                uint32_t b0, b1, b2, b3;
                ldsm_x4_t(b0, b1, b2, b3, &sV[k][n]);
                mma16816(vacc[nt],     af, b0, b1);
                mma16816(vacc[nt + 1], af, b2, b3);
            }
        }
        __syncthreads();
    }

    // ---- epilogue: fp16 ctx[b, n, h*64 + d] ----
    const int b = bh >> 2, h = bh & 3;
    #pragma unroll
    for (int i = 0; i < 2; i++) {
        float inv = 1.0f / rl[i];
        int m = q0 + warp * 16 + (lane >> 2) + i * 8;
        __half* dst = &g_ctxh[((size_t)(b * N_ + m)) * D_ + h * HD_];
        #pragma unroll
        for (int nt = 0; nt < 8; nt++) {
            int c = nt * 8 + (lane & 3) * 2;
            *reinterpret_cast<__half2*>(&dst[c]) =
                __floats2half2_rn(vacc[nt][2 * i] * inv, vacc[nt][2 * i + 1] * inv);
        }
    }
}

// =====================================================================
// LayerNorm(512) + exact GELU: fp32 in (g_h1), fp16 out (g_h1h).
// =====================================================================
__device__ __forceinline__ float gelu_f(float v)
{
    return 0.5f * v * (1.0f + erff(v * 0.70710678118654752440f));
}

__global__ __launch_bounds__(128) void ln_gelu_kernel(
    const float* __restrict__ gam, const float* __restrict__ bet)
{
    __shared__ float red[4];
    const int r = blockIdx.x;
    const float4* row4 = reinterpret_cast<const float4*>(g_h1 + (size_t)r * 512);
    const int tid = threadIdx.x;

    float4 x = row4[tid];
    float s = x.x + x.y + x.z + x.w;
    #pragma unroll
    for (int o = 16; o >= 1; o >>= 1) s += __shfl_xor_sync(0xffffffffu, s, o);
    if ((tid & 31) == 0) red[tid >> 5] = s;
    __syncthreads();
    float mu = (red[0] + red[1] + red[2] + red[3]) * (1.0f / 512.0f);
    __syncthreads();

    float dx0 = x.x - mu, dx1 = x.y - mu, dx2 = x.z - mu, dx3 = x.w - mu;
    float sq = dx0 * dx0 + dx1 * dx1 + dx2 * dx2 + dx3 * dx3;
    #pragma unroll
    for (int o = 16; o >= 1; o >>= 1) sq += __shfl_xor_sync(0xffffffffu, sq, o);
    if ((tid & 31) == 0) red[tid >> 5] = sq;
    __syncthreads();
    float var = (red[0] + red[1] + red[2] + red[3]) * (1.0f / 512.0f);
    float rstd = rsqrtf(var + 1e-5f);

    float4 gv = reinterpret_cast<const float4*>(gam)[tid];
    float4 bv = reinterpret_cast<const float4*>(bet)[tid];
    float o0 = gelu_f(dx0 * rstd * gv.x + bv.x);
    float o1 = gelu_f(dx1 * rstd * gv.y + bv.y);
    float o2 = gelu_f(dx2 * rstd * gv.z + bv.z);
    float o3 = gelu_f(dx3 * rstd * gv.w + bv.w);
    __half* dst = &g_h1h[(size_t)r * 512 + tid * 4];
    *reinterpret_cast<__half2*>(dst)     = __floats2half2_rn(o0, o1);
    *reinterpret_cast<__half2*>(dst + 2) = __floats2half2_rn(o2, o3);
}

// =====================================================================
extern "C" void kernel_launch(void* const* d_in, const int* in_sizes, int n_in,
                              void* d_out, int out_size)
{
    const float* desc   = (const float*)d_in[0];
    const float* kp     = (const float*)d_in[1];
    const float* Wqkv_w = (const float*)d_in[2];
    const float* Wqkv_b = (const float*)d_in[3];
    const float* out_w  = (const float*)d_in[4];
    const float* out_b  = (const float*)d_in[5];
    const float* ffn1_w = (const float*)d_in[6];
    const float* ffn1_b = (const float*)d_in[7];
    const float* ln_g   = (const float*)d_in[8];
    const float* ln_b   = (const float*)d_in[9];
    const float* ffn2_w = (const float*)d_in[10];
    const float* ffn2_b = (const float*)d_in[11];
    float* out = (float*)d_out;

    __half *pwqkv, *poutw, *pffn1, *pffn2, *pctxh, *phcath, *ph1h;
    float* ph1;
    cudaGetSymbolAddress((void**)&pwqkv,  g_wqkv_h);
    cudaGetSymbolAddress((void**)&poutw,  g_outw_h);
    cudaGetSymbolAddress((void**)&pffn1,  g_ffn1_h);
    cudaGetSymbolAddress((void**)&pffn2,  g_ffn2_h);
    cudaGetSymbolAddress((void**)&pctxh,  g_ctxh);
    cudaGetSymbolAddress((void**)&phcath, g_hcath);
    cudaGetSymbolAddress((void**)&ph1,    g_h1);
    cudaGetSymbolAddress((void**)&ph1h,   g_h1h);

    // 0) weight conversions fp32 -> fp16
    f2h<<<192, 256>>>((const float4*)Wqkv_w, pwqkv, 49152);   // 768*256/4
    f2h<<<64,  256>>>((const float4*)out_w,  poutw, 16384);   // 256*256/4
    f2h<<<256, 256>>>((const float4*)ffn1_w, pffn1, 65536);   // 512*512/4
    f2h<<<128, 256>>>((const float4*)ffn2_w, pffn2, 32768);   // 256*512/4
    // 1) descriptors -> fp16 hcat[:, 0:256]
    copy_desc_h<<<4096, 256>>>(reinterpret_cast<const float4*>(desc));
    // 2) fused QKV projection (scatter epilogue -> fp16 q,k,v per-head)
    hgemm_nt<<<dim3(6, 128), 256>>>(phcath, 512, pwqkv, 256, Wqkv_b,
                                    nullptr, 0, 0, nullptr, 2);
    // 3) RoPE in place (q scaled by 1/8)
    rope_half<<<8192, 256>>>(kp);
    // 4) tensor-core flash attention -> fp16 ctx
    attn_mma<<<dim3(N_ / ATT_BM, BH_), 256>>>();
    // 5) out projection -> fp16 hcat[:, 256:512]
    hgemm_nt<<<dim3(2, 128), 256>>>(pctxh, 256, poutw, 256, out_b,
                                    phcath, 512, 256, nullptr, 1);
    // 6) ffn1 -> fp32 h1
    hgemm_nt<<<dim3(4, 128), 256>>>(phcath, 512, pffn1, 512, ffn1_b,
                                    ph1, 512, 0, nullptr, 0);
    // 7) LayerNorm + exact GELU -> fp16 h1h
    ln_gelu_kernel<<<16384, 128>>>(ln_g, ln_b);
    // 8) ffn2 + fp32 residual -> out
    hgemm_nt<<<dim3(2, 128), 256>>>(ph1h, 512, pffn2, 512, ffn2_b,
                                    out, 256, 0, desc, 0);
}

// round 5
// speedup vs baseline: 5.5813x; 1.1011x over previous
#include <cuda_runtime.h>
#include <cuda_fp16.h>
#include <stdint.h>
#include <math.h>

#define B_    4
#define N_    4096
#define D_    256
#define H_    4
#define HD_   64
#define BH_   16            // B*H
#define ROWS_ 16384         // B*N

// ---------------- scratch (static device allocations; no cudaMalloc) ----------------
__device__ __half g_qh[BH_ * N_ * HD_];      // fp16 q (pre-rope -> roped+scaled in place)
__device__ __half g_kh[BH_ * N_ * HD_];      // fp16 k
__device__ __half g_vh[BH_ * N_ * HD_];      // fp16 v
__device__ __half g_ctxh[ROWS_ * D_];        // fp16 attention context
__device__ __half g_hcath[ROWS_ * 2 * D_];   // fp16 [desc | message]
__device__ float  g_h1[ROWS_ * 2 * D_];      // ffn1 out fp32 (LN input)
__device__ __half g_h1h[ROWS_ * 2 * D_];     // LN+GELU out fp16 (ffn2 input)
// fp16 weights
__device__ __half g_wqkv_h[3 * D_ * D_];     // 768x256
__device__ __half g_outw_h[D_ * D_];         // 256x256
__device__ __half g_ffn1_h[2 * D_ * 2 * D_]; // 512x512
__device__ __half g_ffn2_h[D_ * 2 * D_];     // 256x512

// ---------------- primitives ----------------
__device__ __forceinline__ void ldsm_x4(uint32_t& r0, uint32_t& r1, uint32_t& r2, uint32_t& r3,
                                        const __half* p)
{
    uint32_t addr = (uint32_t)__cvta_generic_to_shared(p);
    asm volatile("ldmatrix.sync.aligned.m8n8.x4.shared.b16 {%0,%1,%2,%3}, [%4];"
                 : "=r"(r0), "=r"(r1), "=r"(r2), "=r"(r3) : "r"(addr));
}

__device__ __forceinline__ void ldsm_x4_t(uint32_t& r0, uint32_t& r1, uint32_t& r2, uint32_t& r3,
                                          const __half* p)
{
    uint32_t addr = (uint32_t)__cvta_generic_to_shared(p);
    asm volatile("ldmatrix.sync.aligned.m8n8.x4.trans.shared.b16 {%0,%1,%2,%3}, [%4];"
                 : "=r"(r0), "=r"(r1), "=r"(r2), "=r"(r3) : "r"(addr));
}

__device__ __forceinline__ void mma16816(float* d, const uint32_t* a, uint32_t b0, uint32_t b1)
{
    asm volatile("mma.sync.aligned.m16n8k16.row.col.f32.f16.f16.f32 "
                 "{%0,%1,%2,%3}, {%4,%5,%6,%7}, {%8,%9}, {%0,%1,%2,%3};"
                 : "+f"(d[0]), "+f"(d[1]), "+f"(d[2]), "+f"(d[3])
                 : "r"(a[0]), "r"(a[1]), "r"(a[2]), "r"(a[3]), "r"(b0), "r"(b1));
}

__device__ __forceinline__ void cp16(__half* dst, const __half* src)
{
    uint32_t s = (uint32_t)__cvta_generic_to_shared(dst);
    asm volatile("cp.async.cg.shared.global [%0], [%1], 16;" :: "r"(s), "l"(src));
}
__device__ __forceinline__ void cp_commit() { asm volatile("cp.async.commit_group;"); }
template<int NW> __device__ __forceinline__ void cp_wait()
{
    asm volatile("cp.async.wait_group %0;" :: "n"(NW));
}

// =====================================================================
// fused fp32 -> fp16 weight conversion (all four weights in one launch)
// segments (in float4 units): wqkv 49152 | outw 16384 | ffn1 65536 | ffn2 32768
// =====================================================================
__global__ __launch_bounds__(256) void f2h_all(
    const float4* __restrict__ w0, const float4* __restrict__ w1,
    const float4* __restrict__ w2, const float4* __restrict__ w3)
{
    int i = blockIdx.x * 256 + threadIdx.x;   // 0..163839 (exact grid 640)
    const float4* src;
    __half* dst;
    int off;
    if (i < 49152)        { src = w0; dst = g_wqkv_h; off = i; }
    else if (i < 65536)   { src = w1; dst = g_outw_h; off = i - 49152; }
    else if (i < 131072)  { src = w2; dst = g_ffn1_h; off = i - 65536; }
    else                  { src = w3; dst = g_ffn2_h; off = i - 131072; }
    float4 v = src[off];
    *reinterpret_cast<__half2*>(&dst[off * 4])     = __floats2half2_rn(v.x, v.y);
    *reinterpret_cast<__half2*>(&dst[off * 4 + 2]) = __floats2half2_rn(v.z, v.w);
}

// descriptors -> fp16 hcat[:, 0:256]
__global__ __launch_bounds__(256) void copy_desc_h(const float4* __restrict__ d4)
{
    int idx = blockIdx.x * 256 + threadIdx.x;   // ROWS_*64 float4 chunks (exact grid)
    int r = idx >> 6, c = idx & 63;
    float4 v = d4[idx];
    __half* dst = &g_hcath[(size_t)r * 512 + c * 4];
    *reinterpret_cast<__half2*>(dst)     = __floats2half2_rn(v.x, v.y);
    *reinterpret_cast<__half2*>(dst + 2) = __floats2half2_rn(v.z, v.w);
}

// =====================================================================
// fp16 tensor-core GEMM with cp.async 2-stage pipeline.
// BM=128, BN=128, BK=64, 256 threads = 8 warps (2m x 4n), warp tile 64x32.
// dynamic smem: 2 stages x (A 128x72 + B 128x72) halves = 73728 B
// mode 0: float out (+optional resid)  mode 1: half out  mode 2: qkv scatter
// =====================================================================
#define HG_STG 18432   // halves per stage (A 9216 + B 9216)

__global__ __launch_bounds__(256) void hgemm_nt(
    const __half* __restrict__ A, int lda,
    const __half* __restrict__ W, int K,
    const float* __restrict__ bias,
    void* __restrict__ Cv, int ldc, int colOff,
    const float* __restrict__ resid, int mode)
{
    extern __shared__ __half hsm[];
    const int tid  = threadIdx.x;
    const int warp = tid >> 5, lane = tid & 31;
    const int row0 = blockIdx.y << 7, col0 = blockIdx.x << 7;
    const int m0w  = (warp >> 2) * 64, n0w = (warp & 3) * 32;
    const int lrow = tid >> 3, lc8 = (tid & 7) * 8;   // load lane mapping

    const int KT = K >> 6;

    // preload tiles 0,1
    #pragma unroll
    for (int s = 0; s < 2; s++) {
        __half* pA = hsm + s * HG_STG;
        __half* pB = pA + 9216;
        int k0 = s * 64;
        #pragma unroll
        for (int it = 0; it < 4; it++) {
            int row = lrow + it * 32;
            cp16(pA + row * 72 + lc8, A + (size_t)(row0 + row) * lda + k0 + lc8);
            cp16(pB + row * 72 + lc8, W + (size_t)(col0 + row) * K + k0 + lc8);
        }
        cp_commit();
    }

    float acc[4][4][4] = {};

    for (int t = 0; t < KT; t++) {
        cp_wait<1>();
        __syncthreads();
        const __half* pA = hsm + (t & 1) * HG_STG;
        const __half* pB = pA + 9216;

        #pragma unroll
        for (int kk = 0; kk < 4; kk++) {
            uint32_t af[4][4];
            #pragma unroll
            for (int mt = 0; mt < 4; mt++)
                ldsm_x4(af[mt][0], af[mt][1], af[mt][2], af[mt][3],
                        pA + (m0w + mt * 16 + (lane & 15)) * 72 + kk * 16 + ((lane >> 4) << 3));
            #pragma unroll
            for (int np = 0; np < 2; np++) {
                uint32_t b0, b1, b2, b3;
                ldsm_x4(b0, b1, b2, b3,
                        pB + (n0w + np * 16 + (lane & 7) + ((lane >> 4) << 3)) * 72
                           + kk * 16 + (((lane >> 3) & 1) << 3));
                #pragma unroll
                for (int mt = 0; mt < 4; mt++) {
                    mma16816(acc[mt][np * 2],     af[mt], b0, b1);
                    mma16816(acc[mt][np * 2 + 1], af[mt], b2, b3);
                }
            }
        }
        __syncthreads();

        if (t + 2 < KT) {
            __half* qA = hsm + (t & 1) * HG_STG;
            __half* qB = qA + 9216;
            int k0 = (t + 2) * 64;
            #pragma unroll
            for (int it = 0; it < 4; it++) {
                int row = lrow + it * 32;
                cp16(qA + row * 72 + lc8, A + (size_t)(row0 + row) * lda + k0 + lc8);
                cp16(qB + row * 72 + lc8, W + (size_t)(col0 + row) * K + k0 + lc8);
            }
            cp_commit();
        }
    }

    // ---------------- epilogue ----------------
    if (mode == 2) {
        #pragma unroll
        for (int mt = 0; mt < 4; mt++) {
            #pragma unroll
            for (int nt = 0; nt < 4; nt++) {
                #pragma unroll
                for (int e = 0; e < 4; e++) {
                    int r = row0 + m0w + mt * 16 + (lane >> 2) + ((e >> 1) << 3);
                    int c = col0 + n0w + nt * 8 + (lane & 3) * 2 + (e & 1);
                    float v = acc[mt][nt][e] + bias[c];
                    int b = r >> 12, n = r & (N_ - 1);
                    int h   = c / 192;
                    int rem = c - h * 192;
                    int d   = rem / 3;
                    int cc  = rem - d * 3;
                    size_t dst = ((size_t)(b * H_ + h) * N_ + n) * HD_ + d;
                    __half hv = __float2half(v);
                    if (cc == 0)       g_qh[dst] = hv;
                    else if (cc == 1)  g_kh[dst] = hv;
                    else               g_vh[dst] = hv;
                }
            }
        }
    } else if (mode == 1) {
        __half* C = (__half*)Cv;
        #pragma unroll
        for (int mt = 0; mt < 4; mt++) {
            #pragma unroll
            for (int i = 0; i < 2; i++) {
                int r = row0 + m0w + mt * 16 + (lane >> 2) + i * 8;
                #pragma unroll
                for (int nt = 0; nt < 4; nt++) {
                    int c = col0 + n0w + nt * 8 + (lane & 3) * 2;
                    float v0 = acc[mt][nt][2 * i]     + bias[c];
                    float v1 = acc[mt][nt][2 * i + 1] + bias[c + 1];
                    *reinterpret_cast<__half2*>(&C[(size_t)r * ldc + colOff + c]) =
                        __floats2half2_rn(v0, v1);
                }
            }
        }
    } else {
        float* C = (float*)Cv;
        #pragma unroll
        for (int mt = 0; mt < 4; mt++) {
            #pragma unroll
            for (int i = 0; i < 2; i++) {
                int r = row0 + m0w + mt * 16 + (lane >> 2) + i * 8;
                #pragma unroll
                for (int nt = 0; nt < 4; nt++) {
                    int c = col0 + n0w + nt * 8 + (lane & 3) * 2;
                    float v0 = acc[mt][nt][2 * i]     + bias[c];
                    float v1 = acc[mt][nt][2 * i + 1] + bias[c + 1];
                    if (resid) {
                        const float2 rr = *reinterpret_cast<const float2*>(
                            &resid[(size_t)r * D_ + c]);
                        v0 += rr.x; v1 += rr.y;
                    }
                    *reinterpret_cast<float2*>(&C[(size_t)r * ldc + colOff + c]) =
                        make_float2(v0, v1);
                }
            }
        }
    }
}

// =====================================================================
// RoPE in place on fp16 q/k. q gets 0.125*log2(e) folded (base-2 softmax).
// keypoints: [2, B, 1, N, 64]  (t=0 cos-like, t=1 sin-like)
// =====================================================================
#define QSCALE 0.18033688011112042f   // 0.125 * log2(e)

__global__ __launch_bounds__(256) void rope_half(const float* __restrict__ kp)
{
    int idx = blockIdx.x * 256 + threadIdx.x;   // BH*N*32 pairs (exact grid)
    int i  = idx & 31;
    int n  = (idx >> 5) & (N_ - 1);
    int bh = idx >> 17;
    int b  = bh >> 2;
    int d0 = i * 2;

    const float* kpc = kp + ((size_t)b * N_ + n) * HD_ + d0;
    const float* kps = kpc + (size_t)B_ * N_ * HD_;
    float c0 = kpc[0], c1 = kpc[1];
    float s0 = kps[0], s1 = kps[1];

    size_t off = ((size_t)bh * N_ + n) * HD_ + d0;
    __half2 qv = *reinterpret_cast<__half2*>(&g_qh[off]);
    float x0 = __low2float(qv), x1 = __high2float(qv);
    *reinterpret_cast<__half2*>(&g_qh[off]) =
        __floats2half2_rn((x0 * c0 - x1 * s0) * QSCALE, (x1 * c1 + x0 * s1) * QSCALE);

    __half2 kv = *reinterpret_cast<__half2*>(&g_kh[off]);
    x0 = __low2float(kv); x1 = __high2float(kv);
    *reinterpret_cast<__half2*>(&g_kh[off]) =
        __floats2half2_rn(x0 * c0 - x1 * s0, x1 * c1 + x0 * s1);
}

// =====================================================================
// Tensor-core flash attention, cp.async 2-stage K/V pipeline, base-2 softmax.
// Grid: (N/128, BH), 256 threads = 8 warps. ctx -> fp16.
// =====================================================================
#define ATT_BM 128
#define ATT_BN 64

__global__ __launch_bounds__(256) void attn_mma()
{
    __shared__ __half sK[2][64][72];
    __shared__ __half sV[2][64][72];

    const int tid  = threadIdx.x;
    const int warp = tid >> 5, lane = tid & 31;
    const int bh   = blockIdx.y;
    const int q0   = blockIdx.x * ATT_BM;
    const int lrow = tid >> 3, lc8 = (tid & 7) * 8;

    const __half* Qg = g_qh + (size_t)bh * N_ * HD_;
    const __half* Kg = g_kh + (size_t)bh * N_ * HD_;
    const __half* Vg = g_vh + (size_t)bh * N_ * HD_;

    // ---- stage Q (rows 0-63 -> sK[0], 64-127 -> sV[0]), hoist A-fragments ----
    #pragma unroll
    for (int it = 0; it < 4; it++) {
        int idx = tid + it * 256;              // 0..1023
        int row = idx >> 3, c8 = idx & 7;
        uint4 v = *reinterpret_cast<const uint4*>(Qg + (size_t)(q0 + row) * HD_ + c8 * 8);
        __half* dst = (row < 64) ? &sK[0][row][c8 * 8] : &sV[0][row - 64][c8 * 8];
        *reinterpret_cast<uint4*>(dst) = v;
    }
    __syncthreads();

    uint32_t qf[4][4];
    {
        const __half (*Qa)[72] = (warp < 4) ? sK[0] : sV[0];
        int lr = (warp & 3) * 16 + (lane & 15);
        int ch = (lane >> 4) * 8;
        #pragma unroll
        for (int kk = 0; kk < 4; kk++)
            ldsm_x4(qf[kk][0], qf[kk][1], qf[kk][2], qf[kk][3], &Qa[lr][kk * 16 + ch]);
    }
    __syncthreads();

    // ---- preload K/V tiles 0,1 ----
    #pragma unroll
    for (int s = 0; s < 2; s++) {
        int kt = s * ATT_BN;
        #pragma unroll
        for (int it = 0; it < 2; it++) {
            int row = lrow + it * 32;
            cp16(&sK[s][row][lc8], Kg + (size_t)(kt + row) * HD_ + lc8);
            cp16(&sV[s][row][lc8], Vg + (size_t)(kt + row) * HD_ + lc8);
        }
        cp_commit();
    }

    float vacc[8][4] = {};
    float rm[2] = {-1e30f, -1e30f};
    float rl[2] = {0.0f, 0.0f};

    const int T = N_ / ATT_BN;     // 64
    for (int t = 0; t < T; t++) {
        cp_wait<1>();
        __syncthreads();
        const __half (*cK)[72] = sK[t & 1];
        const __half (*cV)[72] = sV[t & 1];

        // ---- S = Q @ K^T (scores already in log2 units) ----
        float sacc[8][4] = {};
        #pragma unroll
        for (int kk = 0; kk < 4; kk++) {
            #pragma unroll
            for (int nt = 0; nt < 8; nt += 2) {
                int n = nt * 8 + (lane & 7) + ((lane >> 4) << 3);
                int k = kk * 16 + (((lane >> 3) & 1) << 3);
                uint32_t b0, b1, b2, b3;
                ldsm_x4(b0, b1, b2, b3, &cK[n][k]);
                mma16816(sacc[nt],     qf[kk], b0, b1);
                mma16816(sacc[nt + 1], qf[kk], b2, b3);
            }
        }

        // ---- online softmax (base 2) ----
        uint32_t pf[8][2];
        #pragma unroll
        for (int i = 0; i < 2; i++) {
            float mx = -1e30f;
            #pragma unroll
            for (int nt = 0; nt < 8; nt++)
                mx = fmaxf(mx, fmaxf(sacc[nt][2 * i], sacc[nt][2 * i + 1]));
            mx = fmaxf(mx, __shfl_xor_sync(0xffffffffu, mx, 1));
            mx = fmaxf(mx, __shfl_xor_sync(0xffffffffu, mx, 2));
            float nm   = fmaxf(rm[i], mx);
            float corr = exp2f(rm[i] - nm);
            rm[i] = nm;
            float ps = 0.0f;
            #pragma unroll
            for (int nt = 0; nt < 8; nt++) {
                float e0 = exp2f(sacc[nt][2 * i]     - nm);
                float e1 = exp2f(sacc[nt][2 * i + 1] - nm);
                ps += e0 + e1;
                __half2 h = __floats2half2_rn(e0, e1);
                pf[nt][i] = *reinterpret_cast<uint32_t*>(&h);
            }
            ps += __shfl_xor_sync(0xffffffffu, ps, 1);
            ps += __shfl_xor_sync(0xffffffffu, ps, 2);
            rl[i] = rl[i] * corr + ps;
            #pragma unroll
            for (int nt = 0; nt < 8; nt++) {
                vacc[nt][2 * i]     *= corr;
                vacc[nt][2 * i + 1] *= corr;
            }
        }

        // ---- ctx += P @ V ----
        #pragma unroll
        for (int kk2 = 0; kk2 < 4; kk2++) {
            uint32_t af[4] = {pf[2 * kk2][0], pf[2 * kk2][1], pf[2 * kk2 + 1][0], pf[2 * kk2 + 1][1]};
            #pragma unroll
            for (int nt = 0; nt < 8; nt += 2) {
                int k = kk2 * 16 + (lane & 15);
                int n = nt * 8 + ((lane >> 4) << 3);
                uint32_t b0, b1, b2, b3;
                ldsm_x4_t(b0, b1, b2, b3, &cV[k][n]);
                mma16816(vacc[nt],     af, b0, b1);
                mma16816(vacc[nt + 1], af, b2, b3);
            }
        }
        __syncthreads();

        // ---- prefetch tile t+2 into the buffer we just finished ----
        if (t + 2 < T) {
            int s = t & 1;
            int kt = (t + 2) * ATT_BN;
            #pragma unroll
            for (int it = 0; it < 2; it++) {
                int row = lrow + it * 32;
                cp16(&sK[s][row][lc8], Kg + (size_t)(kt + row) * HD_ + lc8);
                cp16(&sV[s][row][lc8], Vg + (size_t)(kt + row) * HD_ + lc8);
            }
            cp_commit();
        }
    }

    // ---- epilogue: fp16 ctx[b, n, h*64 + d] ----
    const int b = bh >> 2, h = bh & 3;
    #pragma unroll
    for (int i = 0; i < 2; i++) {
        float inv = 1.0f / rl[i];
        int m = q0 + warp * 16 + (lane >> 2) + i * 8;
        __half* dst = &g_ctxh[((size_t)(b * N_ + m)) * D_ + h * HD_];
        #pragma unroll
        for (int nt = 0; nt < 8; nt++) {
            int c = nt * 8 + (lane & 3) * 2;
            *reinterpret_cast<__half2*>(&dst[c]) =
                __floats2half2_rn(vacc[nt][2 * i] * inv, vacc[nt][2 * i + 1] * inv);
        }
    }
}

// =====================================================================
// LayerNorm(512) + exact GELU: fp32 in (g_h1), fp16 out (g_h1h).
// =====================================================================
__device__ __forceinline__ float gelu_f(float v)
{
    return 0.5f * v * (1.0f + erff(v * 0.70710678118654752440f));
}

__global__ __launch_bounds__(128) void ln_gelu_kernel(
    const float* __restrict__ gam, const float* __restrict__ bet)
{
    __shared__ float red[4];
    const int r = blockIdx.x;
    const float4* row4 = reinterpret_cast<const float4*>(g_h1 + (size_t)r * 512);
    const int tid = threadIdx.x;

    float4 x = row4[tid];
    float s = x.x + x.y + x.z + x.w;
    #pragma unroll
    for (int o = 16; o >= 1; o >>= 1) s += __shfl_xor_sync(0xffffffffu, s, o);
    if ((tid & 31) == 0) red[tid >> 5] = s;
    __syncthreads();
    float mu = (red[0] + red[1] + red[2] + red[3]) * (1.0f / 512.0f);
    __syncthreads();

    float dx0 = x.x - mu, dx1 = x.y - mu, dx2 = x.z - mu, dx3 = x.w - mu;
    float sq = dx0 * dx0 + dx1 * dx1 + dx2 * dx2 + dx3 * dx3;
    #pragma unroll
    for (int o = 16; o >= 1; o >>= 1) sq += __shfl_xor_sync(0xffffffffu, sq, o);
    if ((tid & 31) == 0) red[tid >> 5] = sq;
    __syncthreads();
    float var = (red[0] + red[1] + red[2] + red[3]) * (1.0f / 512.0f);
    float rstd = rsqrtf(var + 1e-5f);

    float4 gv = reinterpret_cast<const float4*>(gam)[tid];
    float4 bv = reinterpret_cast<const float4*>(bet)[tid];
    float o0 = gelu_f(dx0 * rstd * gv.x + bv.x);
    float o1 = gelu_f(dx1 * rstd * gv.y + bv.y);
    float o2 = gelu_f(dx2 * rstd * gv.z + bv.z);
    float o3 = gelu_f(dx3 * rstd * gv.w + bv.w);
    __half* dst = &g_h1h[(size_t)r * 512 + tid * 4];
    *reinterpret_cast<__half2*>(dst)     = __floats2half2_rn(o0, o1);
    *reinterpret_cast<__half2*>(dst + 2) = __floats2half2_rn(o2, o3);
}

// =====================================================================
extern "C" void kernel_launch(void* const* d_in, const int* in_sizes, int n_in,
                              void* d_out, int out_size)
{
    const float* desc   = (const float*)d_in[0];
    const float* kp     = (const float*)d_in[1];
    const float* Wqkv_w = (const float*)d_in[2];
    const float* Wqkv_b = (const float*)d_in[3];
    const float* out_w  = (const float*)d_in[4];
    const float* out_b  = (const float*)d_in[5];
    const float* ffn1_w = (const float*)d_in[6];
    const float* ffn1_b = (const float*)d_in[7];
    const float* ln_g   = (const float*)d_in[8];
    const float* ln_b   = (const float*)d_in[9];
    const float* ffn2_w = (const float*)d_in[10];
    const float* ffn2_b = (const float*)d_in[11];
    float* out = (float*)d_out;

    __half *pwqkv, *poutw, *pffn1, *pffn2, *pctxh, *phcath, *ph1h;
    float* ph1;
    cudaGetSymbolAddress((void**)&pwqkv,  g_wqkv_h);
    cudaGetSymbolAddress((void**)&poutw,  g_outw_h);
    cudaGetSymbolAddress((void**)&pffn1,  g_ffn1_h);
    cudaGetSymbolAddress((void**)&pffn2,  g_ffn2_h);
    cudaGetSymbolAddress((void**)&pctxh,  g_ctxh);
    cudaGetSymbolAddress((void**)&phcath, g_hcath);
    cudaGetSymbolAddress((void**)&ph1,    g_h1);
    cudaGetSymbolAddress((void**)&ph1h,   g_h1h);

    cudaFuncSetAttribute((const void*)hgemm_nt,
                         cudaFuncAttributeMaxDynamicSharedMemorySize, 2 * HG_STG * 2);

    // 0) weight conversions fp32 -> fp16 (one fused launch)
    f2h_all<<<640, 256>>>((const float4*)Wqkv_w, (const float4*)out_w,
                          (const float4*)ffn1_w, (const float4*)ffn2_w);
    // 1) descriptors -> fp16 hcat[:, 0:256]
    copy_desc_h<<<4096, 256>>>(reinterpret_cast<const float4*>(desc));
    // 2) fused QKV projection (scatter epilogue -> fp16 q,k,v per-head)
    hgemm_nt<<<dim3(6, 128), 256, 2 * HG_STG * 2>>>(phcath, 512, pwqkv, 256, Wqkv_b,
                                                    nullptr, 0, 0, nullptr, 2);
    // 3) RoPE in place (q scaled by 0.125*log2e)
    rope_half<<<8192, 256>>>(kp);
    // 4) tensor-core flash attention -> fp16 ctx
    attn_mma<<<dim3(N_ / ATT_BM, BH_), 256>>>();
    // 5) out projection -> fp16 hcat[:, 256:512]
    hgemm_nt<<<dim3(2, 128), 256, 2 * HG_STG * 2>>>(pctxh, 256, poutw, 256, out_b,
                                                    phcath, 512, 256, nullptr, 1);
    // 6) ffn1 -> fp32 h1
    hgemm_nt<<<dim3(4, 128), 256, 2 * HG_STG * 2>>>(phcath, 512, pffn1, 512, ffn1_b,
                                                    ph1, 512, 0, nullptr, 0);
    // 7) LayerNorm + exact GELU -> fp16 h1h
    ln_gelu_kernel<<<16384, 128>>>(ln_g, ln_b);
    // 8) ffn2 + fp32 residual -> out
    hgemm_nt<<<dim3(2, 128), 256, 2 * HG_STG * 2>>>(ph1h, 512, pffn2, 512, ffn2_b,
                                                    out, 256, 0, desc, 0);
}